// round 1
// baseline (speedup 1.0000x reference)
#include <cuda_runtime.h>
#include <cuda_bf16.h>

// 3x3 PCF shadow visibility:
// vis = (1/9) * sum_{ii,jj in [-1,1]} sigmoid((zbuf[b, clamp(y+ii), clamp(x+jj)] - (z - 0.008)) * 1000)

__global__ __launch_bounds__(256) void shadow_pcf_kernel(
    const float* __restrict__ zbuf,    // [N, S, S]
    const float* __restrict__ depth,   // [N, H, W, K] flattened
    const int2*  __restrict__ xy,      // [N, H, W, K, 2] -> int2 {x, y}
    const int*   __restrict__ image_size, // scalar S on device
    float*       __restrict__ out,     // [N, H, W, K]
    int total,                         // N*H*W*K
    int zbuf_total)                    // N*S*S
{
    int idx = blockIdx.x * blockDim.x + threadIdx.x;
    if (idx >= total) return;

    const int S = *image_size;                    // uniform broadcast load
    const unsigned SS  = (unsigned)S * (unsigned)S;
    const int N   = (int)((unsigned)zbuf_total / SS);   // uniform
    const int HWK = total / N;                          // uniform
    const int b   = idx / HWK;

    const int2 c = xy[idx];
    const float aa = depth[idx] - 0.008f;

    const int x = c.x;
    const int y = c.y;
    const int xm = max(x - 1, 0);
    const int xp = min(x + 1, S - 1);
    const int ym = max(y - 1, 0);
    const int yp = min(y + 1, S - 1);

    const float* zb = zbuf + (size_t)b * (size_t)SS;
    const float* r0 = zb + (size_t)(unsigned)ym * (unsigned)S;
    const float* r1 = zb + (size_t)(unsigned)y  * (unsigned)S;
    const float* r2 = zb + (size_t)(unsigned)yp * (unsigned)S;

    // Issue all 9 gathers up front for memory-level parallelism.
    float v0 = __ldg(r0 + xm);
    float v1 = __ldg(r0 + x);
    float v2 = __ldg(r0 + xp);
    float v3 = __ldg(r1 + xm);
    float v4 = __ldg(r1 + x);
    float v5 = __ldg(r1 + xp);
    float v6 = __ldg(r2 + xm);
    float v7 = __ldg(r2 + x);
    float v8 = __ldg(r2 + xp);

    float acc = 0.0f;
    float vv[9] = {v0, v1, v2, v3, v4, v5, v6, v7, v8};
#pragma unroll
    for (int i = 0; i < 9; ++i) {
        float t = (vv[i] - aa) * 1000.0f;
        // sigmoid(t) = 1 / (1 + exp(-t)); saturates cleanly at both ends.
        acc += 1.0f / (1.0f + __expf(-t));
    }

    out[idx] = acc * (1.0f / 9.0f);
}

extern "C" void kernel_launch(void* const* d_in, const int* in_sizes, int n_in,
                              void* d_out, int out_size) {
    const float* zbuf   = (const float*)d_in[0];   // light_zbuf [N,S,S]
    const float* depth  = (const float*)d_in[1];   // depth_z    [N,H,W,K]
    const int2*  xy     = (const int2*) d_in[2];   // xy         [N,H,W,K,2]
    const int*   imsz   = (const int*)  d_in[3];   // image_size scalar
    float*       out    = (float*)d_out;

    const int total      = in_sizes[1];            // N*H*W*K
    const int zbuf_total = in_sizes[0];            // N*S*S

    const int threads = 256;
    const int blocks  = (total + threads - 1) / threads;
    shadow_pcf_kernel<<<blocks, threads>>>(zbuf, depth, xy, imsz, out,
                                           total, zbuf_total);
}

// round 2
// speedup vs baseline: 1.0850x; 1.0850x over previous
#include <cuda_runtime.h>
#include <cuda_bf16.h>

// 3x3 PCF shadow visibility:
// vis = (1/9) * sum sigmoid((zbuf[b, clamp(y+ii), clamp(x+jj)] - (z - 0.008)) * 1000)

__device__ __forceinline__ float ex2f(float x) {
    float y; asm("ex2.approx.f32 %0, %1;" : "=f"(y) : "f"(x)); return y;
}
__device__ __forceinline__ float rcpf(float x) {
    float y; asm("rcp.approx.f32 %0, %1;" : "=f"(y) : "f"(x)); return y;
}

// sigmoid((v - aa)*1000) = 1 / (1 + exp2(C - v*K)),  K = 1000*log2e, C = aa*K
__device__ __forceinline__ float sig_tap(float v, float C, float K) {
    float u = fmaf(-v, K, C);       // exponent of exp(-(v-aa)*1000) in log2
    return rcpf(1.0f + ex2f(u));    // saturates correctly: ex2->inf => 0, ex2->0 => 1
}

__global__ __launch_bounds__(256) void shadow_pcf_kernel(
    const float* __restrict__ zbuf,       // [N, S, S]
    const float* __restrict__ depth,      // [N, H, W, K]
    const int2*  __restrict__ xy,         // [N, H, W, K] of {x, y}
    const int*   __restrict__ image_size, // scalar S (device)
    float*       __restrict__ out,        // [N, H, W, K]
    int total,                            // N*H*W*K
    int zbuf_total)                       // N*S*S
{
    __shared__ int sm_S, sm_b0, sm_lim;
    __shared__ unsigned sm_SS;

    const int idx = blockIdx.x * blockDim.x + threadIdx.x;

    if (threadIdx.x == 0) {
        int S = *image_size;
        unsigned SS = (unsigned)S * (unsigned)S;
        int N   = (int)((unsigned)zbuf_total / SS);   // one div per block
        int HWK = total / N;                          // one div per block
        int b0  = (blockIdx.x * blockDim.x) / HWK;    // one div per block
        sm_S = S; sm_SS = SS; sm_b0 = b0;
        sm_lim = (b0 + 1) * HWK;
    }
    __syncthreads();

    if (idx >= total) return;

    const int S        = sm_S;
    const unsigned SS  = sm_SS;
    const int b        = sm_b0 + (idx >= sm_lim);     // block straddles <=1 boundary

    const int2 c = __ldg(&xy[idx]);
    const float aa = __ldg(&depth[idx]) - 0.008f;
    const float K = 1000.0f * 1.4426950408889634f;
    const float C = aa * K;

    const int x = c.x;
    const int y = c.y;
    const int ym = max(y - 1, 0);
    const int yp = min(y + 1, S - 1);

    const float* zb = zbuf + (size_t)b * (size_t)SS;
    const float* r0 = zb + (size_t)(unsigned)ym * (unsigned)S;
    const float* r1 = zb + (size_t)(unsigned)y  * (unsigned)S;
    const float* r2 = zb + (size_t)(unsigned)yp * (unsigned)S;

    float acc;

    if ((S & 1) == 0) {
        // Fast path (even S): rows are 8B-aligned. Interior-clamp the column so
        // the 3 taps are contiguous [xi-1, xi+1]; fetch them with two aligned
        // float2 loads, parity-select, then remap for the x==0 / x==S-1 edges.
        const int xi  = min(max(x, 1), S - 2);
        const int c0  = xi - 1;
        int e         = c0 & ~1;
        e             = min(e, S - 4);                // keep window in-bounds
        const bool off = (c0 - e) != 0;               // 0 or 1
        const bool lo  = (x < 1);
        const bool hi  = (x > S - 2);

        float2 p0 = __ldg((const float2*)(r0 + e));
        float2 q0 = __ldg((const float2*)(r0 + e + 2));
        float2 p1 = __ldg((const float2*)(r1 + e));
        float2 q1 = __ldg((const float2*)(r1 + e + 2));
        float2 p2 = __ldg((const float2*)(r2 + e));
        float2 q2 = __ldg((const float2*)(r2 + e + 2));

        acc = 0.0f;
#pragma unroll
        for (int r = 0; r < 3; ++r) {
            float2 p = (r == 0) ? p0 : (r == 1) ? p1 : p2;
            float2 q = (r == 0) ? q0 : (r == 1) ? q1 : q2;
            // window values at positions xi-1, xi, xi+1
            float t0 = off ? p.y : p.x;
            float t1 = off ? q.x : p.y;
            float t2 = off ? q.y : q.x;
            // actual taps (xm, x, xp) after edge clamping
            float vl = hi ? t1 : t0;
            float vm = lo ? t0 : (hi ? t2 : t1);
            float vr = lo ? t1 : t2;
            acc += sig_tap(vl, C, K);
            acc += sig_tap(vm, C, K);
            acc += sig_tap(vr, C, K);
        }
    } else {
        // Generic path (odd S): scalar gathers.
        const int xm = max(x - 1, 0);
        const int xp = min(x + 1, S - 1);
        float v0 = __ldg(r0 + xm), v1 = __ldg(r0 + x), v2 = __ldg(r0 + xp);
        float v3 = __ldg(r1 + xm), v4 = __ldg(r1 + x), v5 = __ldg(r1 + xp);
        float v6 = __ldg(r2 + xm), v7 = __ldg(r2 + x), v8 = __ldg(r2 + xp);
        acc  = sig_tap(v0, C, K) + sig_tap(v1, C, K) + sig_tap(v2, C, K);
        acc += sig_tap(v3, C, K) + sig_tap(v4, C, K) + sig_tap(v5, C, K);
        acc += sig_tap(v6, C, K) + sig_tap(v7, C, K) + sig_tap(v8, C, K);
    }

    out[idx] = acc * (1.0f / 9.0f);
}

extern "C" void kernel_launch(void* const* d_in, const int* in_sizes, int n_in,
                              void* d_out, int out_size) {
    const float* zbuf   = (const float*)d_in[0];
    const float* depth  = (const float*)d_in[1];
    const int2*  xy     = (const int2*) d_in[2];
    const int*   imsz   = (const int*)  d_in[3];
    float*       out    = (float*)d_out;

    const int total      = in_sizes[1];
    const int zbuf_total = in_sizes[0];

    const int threads = 256;
    const int blocks  = (total + threads - 1) / threads;
    shadow_pcf_kernel<<<blocks, threads>>>(zbuf, depth, xy, imsz, out,
                                           total, zbuf_total);
}

// round 3
// speedup vs baseline: 1.1091x; 1.0221x over previous
#include <cuda_runtime.h>
#include <cuda_bf16.h>

// 3x3 PCF shadow visibility:
// vis = (1/9) * sum sigmoid((zbuf[b, clamp(y+ii), clamp(x+jj)] - (z - 0.008)) * 1000)

__device__ __forceinline__ float ex2f(float x) {
    float y; asm("ex2.approx.f32 %0, %1;" : "=f"(y) : "f"(x)); return y;
}
__device__ __forceinline__ float rcpf(float x) {
    float y; asm("rcp.approx.f32 %0, %1;" : "=f"(y) : "f"(x)); return y;
}

// sigmoid((v - aa)*1000) = 1 / (1 + exp2(C - v*K)),  K = 1000*log2e, C = aa*K
__device__ __forceinline__ float sig_tap(float v, float C, float K) {
    float u = fmaf(-v, K, C);
    return rcpf(1.0f + ex2f(u));
}

__global__ __launch_bounds__(256) void shadow_pcf_kernel(
    const float* __restrict__ zbuf,       // [N, S, S]
    const float* __restrict__ depth,      // [N, H, W, K]
    const int2*  __restrict__ xy,         // [N, H, W, K] of {x, y}
    const int*   __restrict__ image_size, // scalar S (device)
    float*       __restrict__ out,        // [N, H, W, K]
    int total,                            // N*H*W*K
    int zbuf_total)                       // N*S*S
{
    __shared__ int sm_S, sm_b0, sm_lim;
    __shared__ unsigned sm_SS;

    const int idx = blockIdx.x * blockDim.x + threadIdx.x;

    if (threadIdx.x == 0) {
        int S = *image_size;
        unsigned SS = (unsigned)S * (unsigned)S;
        int N   = (int)((unsigned)zbuf_total / SS);
        int HWK = total / N;
        int b0  = (blockIdx.x * blockDim.x) / HWK;
        sm_S = S; sm_SS = SS; sm_b0 = b0;
        sm_lim = (b0 + 1) * HWK;
    }
    __syncthreads();

    if (idx >= total) return;

    const int S        = sm_S;
    const unsigned SS  = sm_SS;
    const int b        = sm_b0 + (idx >= sm_lim);   // block straddles <=1 boundary

    const int2 c = __ldg(&xy[idx]);
    const float aa = __ldg(&depth[idx]) - 0.008f;
    const float K = 1000.0f * 1.4426950408889634f;
    const float C = aa * K;

    const int x = c.x;
    const int y = c.y;
    const int ym = max(y - 1, 0);
    const int yp = min(y + 1, S - 1);

    const float* zb = zbuf + (size_t)b * (size_t)SS;
    const float* r0 = zb + (size_t)(unsigned)ym * (unsigned)S;
    const float* r1 = zb + (size_t)(unsigned)y  * (unsigned)S;
    const float* r2 = zb + (size_t)(unsigned)yp * (unsigned)S;

    float acc = 0.0f;

    if ((S & 3) == 0) {
        // Fast path (S % 4 == 0): every row is 16B-aligned. Interior-clamp the
        // column so the taps are the contiguous triple [c0, c0+2]; fetch the
        // aligned float4 chunk containing c0 and, only when the window
        // overflows it (d >= 2, ~50%), a predicated aligned float2 at e16+4.
        // Proof of bounds: d>=2 requires c0 >= e16+2 and c0 <= S-3, so
        // e16 <= S-5 -> (e16 multiple of 4, S even) e16 <= S-6 -> e16+5 <= S-1.
        const int xi  = min(max(x, 1), S - 2);
        const int c0  = xi - 1;                 // in [0, S-3]
        const int e16 = c0 & ~3;
        const int d   = c0 - e16;               // 0..3
        const bool need_q = (d >= 2);
        const bool d2 = (d & 2) != 0;
        const bool d1 = (d & 1) != 0;
        const bool lo = (x < 1);
        const bool hi = (x > S - 2);

        const float* rows[3] = {r0, r1, r2};
        float4 P[3];
        float2 Q[3];
#pragma unroll
        for (int r = 0; r < 3; ++r) {
            P[r] = __ldg((const float4*)(rows[r] + e16));
            Q[r] = make_float2(0.0f, 0.0f);
            if (need_q) Q[r] = __ldg((const float2*)(rows[r] + e16 + 4));
        }

#pragma unroll
        for (int r = 0; r < 3; ++r) {
            // select window [c0, c0+2] out of the 6 fetched floats
            float g0 = d2 ? P[r].z : P[r].x;
            float g1 = d2 ? P[r].w : P[r].y;
            float g2 = d2 ? Q[r].x : P[r].z;
            float g3 = d2 ? Q[r].y : P[r].w;
            float t0 = d1 ? g1 : g0;
            float t1 = d1 ? g2 : g1;
            float t2 = d1 ? g3 : g2;
            // remap for x==0 / x==S-1 edge clamping
            float vl = hi ? t1 : t0;
            float vm = lo ? t0 : (hi ? t2 : t1);
            float vr = lo ? t1 : t2;
            acc += sig_tap(vl, C, K);
            acc += sig_tap(vm, C, K);
            acc += sig_tap(vr, C, K);
        }
    } else {
        // Generic path: scalar gathers.
        const int xm = max(x - 1, 0);
        const int xp = min(x + 1, S - 1);
        float v0 = __ldg(r0 + xm), v1 = __ldg(r0 + x), v2 = __ldg(r0 + xp);
        float v3 = __ldg(r1 + xm), v4 = __ldg(r1 + x), v5 = __ldg(r1 + xp);
        float v6 = __ldg(r2 + xm), v7 = __ldg(r2 + x), v8 = __ldg(r2 + xp);
        acc  = sig_tap(v0, C, K) + sig_tap(v1, C, K) + sig_tap(v2, C, K);
        acc += sig_tap(v3, C, K) + sig_tap(v4, C, K) + sig_tap(v5, C, K);
        acc += sig_tap(v6, C, K) + sig_tap(v7, C, K) + sig_tap(v8, C, K);
    }

    out[idx] = acc * (1.0f / 9.0f);
}

extern "C" void kernel_launch(void* const* d_in, const int* in_sizes, int n_in,
                              void* d_out, int out_size) {
    const float* zbuf   = (const float*)d_in[0];
    const float* depth  = (const float*)d_in[1];
    const int2*  xy     = (const int2*) d_in[2];
    const int*   imsz   = (const int*)  d_in[3];
    float*       out    = (float*)d_out;

    const int total      = in_sizes[1];
    const int zbuf_total = in_sizes[0];

    const int threads = 256;
    const int blocks  = (total + threads - 1) / threads;
    shadow_pcf_kernel<<<blocks, threads>>>(zbuf, depth, xy, imsz, out,
                                           total, zbuf_total);
}

// round 4
// speedup vs baseline: 1.1114x; 1.0021x over previous
#include <cuda_runtime.h>
#include <cuda_bf16.h>

// 3x3 PCF shadow visibility, 2 pixels per thread:
// vis = (1/9) * sum sigmoid((zbuf[b, clamp(y+ii), clamp(x+jj)] - (z - 0.008)) * 1000)

__device__ __forceinline__ float ex2f(float x) {
    float y; asm("ex2.approx.f32 %0, %1;" : "=f"(y) : "f"(x)); return y;
}
__device__ __forceinline__ float rcpf(float x) {
    float y; asm("rcp.approx.f32 %0, %1;" : "=f"(y) : "f"(x)); return y;
}

// p_i = 1 + exp2(min(u_i, 30)); sum of 1/p over a quad with one rcp.
__device__ __forceinline__ float quad_sum(float p0, float p1, float p2, float p3) {
    float a = p0 * p1;
    float b = p2 * p3;
    float num = (p0 + p1) * b + (p2 + p3) * a;
    return num * rcpf(a * b);
}
__device__ __forceinline__ float pval(float v, float C, float K) {
    float u = fmaf(-v, K, C);          // log2 of exp(-(v-aa)*1000)
    u = fminf(u, 30.0f);               // keep 4-way products finite
    return 1.0f + ex2f(u);
}

__global__ __launch_bounds__(256) void shadow_pcf2_kernel(
    const float* __restrict__ zbuf,       // [N, S, S]
    const float* __restrict__ depth,      // [N, H, W, K]
    const int*   __restrict__ xy,         // [N, H, W, K, 2]
    const int*   __restrict__ image_size, // scalar S (device)
    float*       __restrict__ out,        // [N, H, W, K]
    int total,                            // N*H*W*K
    int zbuf_total)                       // N*S*S
{
    __shared__ int sm_S, sm_b0, sm_lim;
    __shared__ unsigned sm_SS;

    const int i    = blockIdx.x * blockDim.x + threadIdx.x;
    const int idx0 = 2 * i;

    if (threadIdx.x == 0) {
        int S = *image_size;
        unsigned SS = (unsigned)S * (unsigned)S;
        int N   = (int)((unsigned)zbuf_total / SS);
        int HWK = total / N;
        int base = blockIdx.x * blockDim.x * 2;
        int b0 = base / HWK;
        sm_S = S; sm_SS = SS; sm_b0 = b0;
        sm_lim = (b0 + 1) * HWK;
    }
    __syncthreads();

    if (idx0 >= total) return;

    const int S       = sm_S;
    const unsigned SS = sm_SS;
    const int b0v     = sm_b0;
    const int lim     = sm_lim;
    const bool has2   = (idx0 + 1) < total;

    const float Kc = 1000.0f * 1.4426950408889634f;

    int xs[2], ys[2];
    float C_[2];
    if (has2) {
        int4  cc = __ldg((const int4*)(xy + 2 * idx0));      // x0,y0,x1,y1
        float2 dd = __ldg((const float2*)(depth + idx0));
        xs[0] = cc.x; ys[0] = cc.y; xs[1] = cc.z; ys[1] = cc.w;
        C_[0] = (dd.x - 0.008f) * Kc;
        C_[1] = (dd.y - 0.008f) * Kc;
    } else {
        int2 cc = __ldg((const int2*)(xy + 2 * idx0));
        xs[0] = cc.x; ys[0] = cc.y; xs[1] = 0; ys[1] = 0;
        C_[0] = (__ldg(depth + idx0) - 0.008f) * Kc;
        C_[1] = 0.0f;
    }

    float acc[2] = {0.0f, 0.0f};

    if ((S & 3) == 0) {
        // ---- fast path: rows 16B-aligned ----
        const float* rows[2][3];
        bool d2_[2], d1_[2], lo_[2], hi_[2], nq_[2];

#pragma unroll
        for (int p = 0; p < 2; ++p) {
            const int idx = idx0 + p;
            const int b   = b0v + (idx >= lim);
            const int x = xs[p], y = ys[p];
            const int ym = max(y - 1, 0);
            const int yp = min(y + 1, S - 1);
            const int xi = min(max(x, 1), S - 2);
            const int c0 = xi - 1;
            const int e16 = c0 & ~3;
            const int d   = c0 - e16;          // 0..3
            nq_[p] = (d >= 2);
            d2_[p] = (d & 2) != 0;
            d1_[p] = (d & 1) != 0;
            lo_[p] = (x < 1);
            hi_[p] = (x > S - 2);
            const float* zb = zbuf + (size_t)b * (size_t)SS;
            rows[p][0] = zb + (size_t)(unsigned)ym * (unsigned)S + e16;
            rows[p][1] = zb + (size_t)(unsigned)y  * (unsigned)S + e16;
            rows[p][2] = zb + (size_t)(unsigned)yp * (unsigned)S + e16;
        }

        // Issue all gathers before any consumption (max MLP).
        float4 P[2][3];
        float2 Q[2][3];
#pragma unroll
        for (int p = 0; p < 2; ++p)
#pragma unroll
            for (int r = 0; r < 3; ++r)
                P[p][r] = __ldg((const float4*)rows[p][r]);
#pragma unroll
        for (int p = 0; p < 2; ++p)
#pragma unroll
            for (int r = 0; r < 3; ++r) {
                Q[p][r] = make_float2(0.0f, 0.0f);
                if (nq_[p]) Q[p][r] = __ldg((const float2*)(rows[p][r] + 4));
            }

#pragma unroll
        for (int p = 0; p < 2; ++p) {
            const bool d2 = d2_[p], d1 = d1_[p], lo = lo_[p], hi = hi_[p];
            const float C = C_[p];
            float pv[9];
#pragma unroll
            for (int r = 0; r < 3; ++r) {
                float g0 = d2 ? P[p][r].z : P[p][r].x;
                float g1 = d2 ? P[p][r].w : P[p][r].y;
                float g2 = d2 ? Q[p][r].x : P[p][r].z;
                float g3 = d2 ? Q[p][r].y : P[p][r].w;
                float t0 = d1 ? g1 : g0;
                float t1 = d1 ? g2 : g1;
                float t2 = d1 ? g3 : g2;
                float vl = hi ? t1 : t0;
                float vm = lo ? t0 : (hi ? t2 : t1);
                float vr = lo ? t1 : t2;
                pv[3 * r + 0] = pval(vl, C, Kc);
                pv[3 * r + 1] = pval(vm, C, Kc);
                pv[3 * r + 2] = pval(vr, C, Kc);
            }
            acc[p] = quad_sum(pv[0], pv[1], pv[2], pv[3])
                   + quad_sum(pv[4], pv[5], pv[6], pv[7])
                   + rcpf(pv[8]);
        }
    } else {
        // ---- generic path: scalar gathers ----
#pragma unroll
        for (int p = 0; p < 2; ++p) {
            const int idx = idx0 + p;
            if (p == 1 && !has2) break;
            const int b = b0v + (idx >= lim);
            const int x = xs[p], y = ys[p];
            const int xm = max(x - 1, 0), xp = min(x + 1, S - 1);
            const int ym = max(y - 1, 0), yp = min(y + 1, S - 1);
            const float* zb = zbuf + (size_t)b * (size_t)SS;
            const float* r0 = zb + (size_t)(unsigned)ym * (unsigned)S;
            const float* r1 = zb + (size_t)(unsigned)y  * (unsigned)S;
            const float* r2 = zb + (size_t)(unsigned)yp * (unsigned)S;
            const float C = C_[p];
            float pv[9];
            pv[0] = pval(__ldg(r0 + xm), C, Kc);
            pv[1] = pval(__ldg(r0 + x ), C, Kc);
            pv[2] = pval(__ldg(r0 + xp), C, Kc);
            pv[3] = pval(__ldg(r1 + xm), C, Kc);
            pv[4] = pval(__ldg(r1 + x ), C, Kc);
            pv[5] = pval(__ldg(r1 + xp), C, Kc);
            pv[6] = pval(__ldg(r2 + xm), C, Kc);
            pv[7] = pval(__ldg(r2 + x ), C, Kc);
            pv[8] = pval(__ldg(r2 + xp), C, Kc);
            acc[p] = quad_sum(pv[0], pv[1], pv[2], pv[3])
                   + quad_sum(pv[4], pv[5], pv[6], pv[7])
                   + rcpf(pv[8]);
        }
    }

    if (has2) {
        float2 o = make_float2(acc[0] * (1.0f / 9.0f), acc[1] * (1.0f / 9.0f));
        *(float2*)(out + idx0) = o;
    } else {
        out[idx0] = acc[0] * (1.0f / 9.0f);
    }
}

extern "C" void kernel_launch(void* const* d_in, const int* in_sizes, int n_in,
                              void* d_out, int out_size) {
    const float* zbuf   = (const float*)d_in[0];
    const float* depth  = (const float*)d_in[1];
    const int*   xy     = (const int*)  d_in[2];
    const int*   imsz   = (const int*)  d_in[3];
    float*       out    = (float*)d_out;

    const int total      = in_sizes[1];
    const int zbuf_total = in_sizes[0];

    const int threads = 256;
    const int pairs   = (total + 1) / 2;
    const int blocks  = (pairs + threads - 1) / threads;
    shadow_pcf2_kernel<<<blocks, threads>>>(zbuf, depth, xy, imsz, out,
                                            total, zbuf_total);
}